// round 6
// baseline (speedup 1.0000x reference)
#include <cuda_runtime.h>
#include <math.h>

#define Bsz 32
#define Nf  4096
#define Kv  1024
#define Dm  1024
#define Hh  16
#define MAXF 4096

typedef unsigned long long u64;

// Single static scratch arena — no allocations anywhere. (84 MB)
__device__ float g_scratch[20971520];

// kv-region offset inside wpart (frame: 16 chunks, kv: 4 chunks)
#define WKV_OFF 8388608

// ---- f32x2 packed helpers ---------------------------------------------------
__device__ __forceinline__ void ffma2(u64& d, u64 a, u64 b)
{
    asm("fma.rn.f32x2 %0, %1, %2, %0;" : "+l"(d) : "l"(a), "l"(b));
}
__device__ __forceinline__ u64 dup2(float a)
{
    u64 r; asm("mov.b64 %0, {%1,%1};" : "=l"(r) : "f"(a)); return r;
}
__device__ __forceinline__ float sum2(u64 v)
{
    float lo, hi; asm("mov.b64 {%0,%1}, %2;" : "=f"(lo), "=f"(hi) : "l"(v));
    return lo + hi;
}

// ---------------- mean over frame tokens (split into 16 partials) -------------
__global__ void k_mean_part(const float* __restrict__ frame, float* __restrict__ mpart)
{
    int b = blockIdx.x, sp = blockIdx.y, tid = threadIdx.x;
    const float4* fp = (const float4*)(frame + ((size_t)b * Nf + sp * 256) * Dm) + tid;
    float4 acc = make_float4(0.f, 0.f, 0.f, 0.f);
    #pragma unroll 4
    for (int n = 0; n < 256; n++) {
        float4 v = fp[(size_t)n * 256];
        acc.x += v.x; acc.y += v.y; acc.z += v.z; acc.w += v.w;
    }
    ((float4*)(mpart + ((size_t)sp * Bsz + b) * Dm))[tid] = acc;
}

// ---------------- q init ------------------------------------------------------
__global__ void k_qinit(const float* __restrict__ mpart, const float* __restrict__ mi,
                        const float* __restrict__ qb, const float* __restrict__ role,
                        const float* __restrict__ tw, const int* __restrict__ fidx,
                        float* __restrict__ q)
{
    int b = blockIdx.x, tid = threadIdx.x;
    float4 m = make_float4(0.f, 0.f, 0.f, 0.f);
    for (int sp = 0; sp < 16; sp++) {
        float4 v = ((const float4*)(mpart + ((size_t)sp * Bsz + b) * Dm))[tid];
        m.x += v.x; m.y += v.y; m.z += v.z; m.w += v.w;
    }
    const float inv = 1.f / (float)Nf;
    int t = fidx[b]; t = t < 0 ? 0 : (t > MAXF - 1 ? MAXF - 1 : t);
    float4 te = ((const float4*)(tw + (size_t)t * Dm))[tid];
    float4 q0 = ((const float4*)qb)[tid];
    float4 q1 = ((const float4*)(qb + Dm))[tid];
    float4 r0 = ((const float4*)role)[tid];
    float4 r1 = ((const float4*)(role + Dm))[tid];
    float4 mv = ((const float4*)(mi + (size_t)b * Dm))[tid];
    float4 o0, o1;
    o0.x = m.x * inv + q0.x + r0.x + te.x;  o0.y = m.y * inv + q0.y + r0.y + te.y;
    o0.z = m.z * inv + q0.z + r0.z + te.z;  o0.w = m.w * inv + q0.w + r0.w + te.w;
    o1.x = mv.x + q1.x + r1.x + te.x;       o1.y = mv.y + q1.y + r1.y + te.y;
    o1.z = mv.z + q1.z + r1.z + te.z;       o1.w = mv.w + q1.w + r1.w + te.w;
    ((float4*)(q + (size_t)b * 2 * Dm))[tid] = o0;
    ((float4*)(q + (size_t)b * 2 * Dm + Dm))[tid] = o1;
}

// ---------------- LayerNorm (standalone; only used once at init) -------------
__global__ void k_ln(const float* __restrict__ in, const float* __restrict__ g,
                     const float* __restrict__ b, float* __restrict__ outp)
{
    __shared__ float2 red[256];
    int row = blockIdx.x, tid = threadIdx.x;
    float4 v = ((const float4*)(in + (size_t)row * Dm))[tid];
    float s = v.x + v.y + v.z + v.w;
    float sq = v.x * v.x + v.y * v.y + v.z * v.z + v.w * v.w;
    red[tid] = make_float2(s, sq); __syncthreads();
    for (int st = 128; st > 0; st >>= 1) {
        if (tid < st) { red[tid].x += red[tid + st].x; red[tid].y += red[tid + st].y; }
        __syncthreads();
    }
    float mean = red[0].x * (1.f / 1024.f);
    float var  = red[0].y * (1.f / 1024.f) - mean * mean;
    float rstd = rsqrtf(var + 1e-5f);
    float4 gv = ((const float4*)g)[tid];
    float4 bv = ((const float4*)b)[tid];
    float4 o;
    o.x = (v.x - mean) * rstd * gv.x + bv.x;
    o.y = (v.y - mean) * rstd * gv.y + bv.y;
    o.z = (v.z - mean) * rstd * gv.z + bv.z;
    o.w = (v.w - mean) * rstd * gv.w + bv.w;
    ((float4*)(outp + (size_t)row * Dm))[tid] = o;
}

// ---------------- pipelined GEMM, pairable via blockIdx.y --------------------
// part[ks][mbase+m][n] = Ause[m-tile, kchunk] @ Wuse[n-tile, kchunk]^T
template<int MT>
__global__ __launch_bounds__(256) void k_gemmp2(
    const float* __restrict__ A, int lda,
    const float* __restrict__ W, int K,
    const float* __restrict__ A2, const float* __restrict__ W2,
    float* __restrict__ part, int N, int kchunk, int Mtot)
{
    __shared__ __align__(16) u64   As2[2][16 * MT];
    __shared__ __align__(16) float Ws [2][16 * 128];
    const int tid = threadIdx.x;
    const int tx = tid & 15, ty = tid >> 4;
    const int MR = MT / 16;                      // 4 (MT=64) or 2 (MT=32)
    const int n0 = blockIdx.x * 128;
    const float* Ab = blockIdx.y ? A2 : A;
    const float* Wb = blockIdx.y ? W2 : W;
    const int mbase = blockIdx.y * MT;
    const int ks = blockIdx.z;

    u64 acc[MR][4];
    #pragma unroll
    for (int i = 0; i < MR; i++)
        #pragma unroll
        for (int j = 0; j < 4; j++) acc[i][j] = 0ULL;

    const int ar = tid >> 2, ac = (tid & 3) << 2;
    const bool aload = (MT == 64) || (tid < 128);
    const int wr = tid & 127, wc = (tid >> 7) << 3;
    const float* Ap = Ab + (size_t)(aload ? ar : 0) * lda;
    const float* Wp = Wb + (size_t)(n0 + wr) * K;
    const int kk0 = ks * kchunk;
    const int iters = kchunk >> 4;

    float4 av = make_float4(0.f, 0.f, 0.f, 0.f), w0, w1;
    if (aload) av = *(const float4*)(Ap + kk0 + ac);
    w0 = *(const float4*)(Wp + kk0 + wc);
    w1 = *(const float4*)(Wp + kk0 + wc + 4);
    if (aload) {
        As2[0][(ac + 0) * MT + ar] = dup2(av.x);
        As2[0][(ac + 1) * MT + ar] = dup2(av.y);
        As2[0][(ac + 2) * MT + ar] = dup2(av.z);
        As2[0][(ac + 3) * MT + ar] = dup2(av.w);
    }
    Ws[0][(wc + 0) * 128 + wr] = w0.x; Ws[0][(wc + 1) * 128 + wr] = w0.y;
    Ws[0][(wc + 2) * 128 + wr] = w0.z; Ws[0][(wc + 3) * 128 + wr] = w0.w;
    Ws[0][(wc + 4) * 128 + wr] = w1.x; Ws[0][(wc + 5) * 128 + wr] = w1.y;
    Ws[0][(wc + 6) * 128 + wr] = w1.z; Ws[0][(wc + 7) * 128 + wr] = w1.w;
    __syncthreads();

    for (int it = 0; it < iters; it++) {
        int cur = it & 1;
        if (it + 1 < iters) {
            int kk = kk0 + (it + 1) * 16;
            if (aload) av = *(const float4*)(Ap + kk + ac);
            w0 = *(const float4*)(Wp + kk + wc);
            w1 = *(const float4*)(Wp + kk + wc + 4);
        }
        #pragma unroll
        for (int k = 0; k < 16; k++) {
            ulonglong2 a01 = *(const ulonglong2*)&As2[cur][k * MT + ty * MR];
            ulonglong2 wA  = *(const ulonglong2*)&Ws[cur][k * 128 + tx * 8];
            ulonglong2 wB  = *(const ulonglong2*)&Ws[cur][k * 128 + tx * 8 + 4];
            ffma2(acc[0][0], a01.x, wA.x); ffma2(acc[0][1], a01.x, wA.y);
            ffma2(acc[0][2], a01.x, wB.x); ffma2(acc[0][3], a01.x, wB.y);
            ffma2(acc[1][0], a01.y, wA.x); ffma2(acc[1][1], a01.y, wA.y);
            ffma2(acc[1][2], a01.y, wB.x); ffma2(acc[1][3], a01.y, wB.y);
            if (MR == 4) {
                ulonglong2 a23 = *(const ulonglong2*)&As2[cur][k * MT + ty * MR + 2];
                ffma2(acc[2][0], a23.x, wA.x); ffma2(acc[2][1], a23.x, wA.y);
                ffma2(acc[2][2], a23.x, wB.x); ffma2(acc[2][3], a23.x, wB.y);
                ffma2(acc[3][0], a23.y, wA.x); ffma2(acc[3][1], a23.y, wA.y);
                ffma2(acc[3][2], a23.y, wB.x); ffma2(acc[3][3], a23.y, wB.y);
            }
        }
        if (it + 1 < iters) {
            int nb = cur ^ 1;
            if (aload) {
                As2[nb][(ac + 0) * MT + ar] = dup2(av.x);
                As2[nb][(ac + 1) * MT + ar] = dup2(av.y);
                As2[nb][(ac + 2) * MT + ar] = dup2(av.z);
                As2[nb][(ac + 3) * MT + ar] = dup2(av.w);
            }
            Ws[nb][(wc + 0) * 128 + wr] = w0.x; Ws[nb][(wc + 1) * 128 + wr] = w0.y;
            Ws[nb][(wc + 2) * 128 + wr] = w0.z; Ws[nb][(wc + 3) * 128 + wr] = w0.w;
            Ws[nb][(wc + 4) * 128 + wr] = w1.x; Ws[nb][(wc + 5) * 128 + wr] = w1.y;
            Ws[nb][(wc + 6) * 128 + wr] = w1.z; Ws[nb][(wc + 7) * 128 + wr] = w1.w;
        }
        __syncthreads();
    }

    float* P = part + ((size_t)ks * Mtot + mbase + ty * MR) * N + n0 + tx * 8;
    #pragma unroll
    for (int i = 0; i < MR; i++) {
        ulonglong2 v0; v0.x = acc[i][0]; v0.y = acc[i][1];
        ulonglong2 v1; v1.x = acc[i][2]; v1.y = acc[i][3];
        *(ulonglong2*)(P + (size_t)i * N)     = v0;
        *(ulonglong2*)(P + (size_t)i * N + 4) = v1;
    }
}

__device__ __forceinline__ float gelu_exact(float x)
{
    return 0.5f * x * (1.f + erff(x * 0.70710678118654752f));
}

// generic reduce (no LN): sa_in, ffn1
__global__ void k_gemm_reduce(const float* __restrict__ part,
                              float* __restrict__ C, int ldc,
                              const float* __restrict__ bias,
                              int M, int N, int nsplit, int act)
{
    int n = blockIdx.x * 256 + threadIdx.x;
    int m = blockIdx.y;
    if (n >= N) return;
    float s = 0.f;
    for (int ks = 0; ks < nsplit; ks++) s += part[((size_t)ks * M + m) * N + n];
    s += bias[n];
    if (act) s = gelu_exact(s);
    C[(size_t)m * ldc + n] = s;
}

// paired reduce (qproj): part has M=64 (g rows 0-31, s rows 32-63), N=1024
__global__ void k_reduce_pair(const float* __restrict__ part, int nsplit,
                              const float* __restrict__ bA, const float* __restrict__ bB,
                              float* __restrict__ CA, float* __restrict__ CB)
{
    int n = blockIdx.x * 256 + threadIdx.x;
    int m = blockIdx.y;
    float s = 0.f;
    for (int ks = 0; ks < nsplit; ks++) s += part[((size_t)ks * 64 + m) * 1024 + n];
    if (m < 32) CA[(size_t)m * 1024 + n] = s + bA[n];
    else        CB[(size_t)(m - 32) * 1024 + n] = s + bB[n];
}

// reduce + bias + residual -> C(row), then LayerNorm -> X(row). N==1024.
__global__ void k_reduce_ln(const float* __restrict__ part, int M, int nsplit,
                            const float* __restrict__ bias,
                            float* __restrict__ C, int ldc,
                            const float* __restrict__ lng, const float* __restrict__ lnb,
                            float* __restrict__ X, int ldx)
{
    __shared__ float2 red[256];
    int m = blockIdx.x, tid = threadIdx.x;
    float4 s4 = make_float4(0.f, 0.f, 0.f, 0.f);
    for (int ks = 0; ks < nsplit; ks++) {
        float4 v = ((const float4*)(part + ((size_t)ks * M + m) * 1024))[tid];
        s4.x += v.x; s4.y += v.y; s4.z += v.z; s4.w += v.w;
    }
    float4 bb = ((const float4*)bias)[tid];
    float4 rr = ((const float4*)(C + (size_t)m * ldc))[tid];
    s4.x += bb.x + rr.x; s4.y += bb.y + rr.y;
    s4.z += bb.z + rr.z; s4.w += bb.w + rr.w;
    ((float4*)(C + (size_t)m * ldc))[tid] = s4;
    float s = s4.x + s4.y + s4.z + s4.w;
    float sq = s4.x * s4.x + s4.y * s4.y + s4.z * s4.z + s4.w * s4.w;
    red[tid] = make_float2(s, sq); __syncthreads();
    for (int st = 128; st > 0; st >>= 1) {
        if (tid < st) { red[tid].x += red[tid + st].x; red[tid].y += red[tid + st].y; }
        __syncthreads();
    }
    float mean = red[0].x * (1.f / 1024.f);
    float var  = red[0].y * (1.f / 1024.f) - mean * mean;
    float rstd = rsqrtf(var + 1e-5f);
    float4 gv = ((const float4*)lng)[tid];
    float4 bv = ((const float4*)lnb)[tid];
    float4 o;
    o.x = (s4.x - mean) * rstd * gv.x + bv.x;
    o.y = (s4.y - mean) * rstd * gv.y + bv.y;
    o.z = (s4.z - mean) * rstd * gv.z + bv.z;
    o.w = (s4.w - mean) * rstd * gv.w + bv.w;
    ((float4*)(X + (size_t)m * ldx))[tid] = o;
}

// paired reduce+res+LN for out-projections (g rows 0-31, s rows 32-63 in part)
__global__ void k_reduce_ln_pair(const float* __restrict__ part, int nsplit,
                                 const float* __restrict__ bA, const float* __restrict__ bB,
                                 float* __restrict__ q,
                                 const float* __restrict__ lng, const float* __restrict__ lnb,
                                 float* __restrict__ x)
{
    __shared__ float2 red[256];
    int m = blockIdx.x, tid = threadIdx.x;
    float* qrow; const float* bias; float* xrow;
    if (m < 32) { qrow = q + (size_t)m * 2048; bias = bA; xrow = x + (size_t)m * 2048; }
    else { qrow = q + (size_t)(m - 32) * 2048 + 1024; bias = bB; xrow = x + (size_t)(m - 32) * 2048 + 1024; }
    float4 s4 = make_float4(0.f, 0.f, 0.f, 0.f);
    for (int ks = 0; ks < nsplit; ks++) {
        float4 v = ((const float4*)(part + ((size_t)ks * 64 + m) * 1024))[tid];
        s4.x += v.x; s4.y += v.y; s4.z += v.z; s4.w += v.w;
    }
    float4 bb = ((const float4*)bias)[tid];
    float4 rr = ((const float4*)qrow)[tid];
    s4.x += bb.x + rr.x; s4.y += bb.y + rr.y;
    s4.z += bb.z + rr.z; s4.w += bb.w + rr.w;
    ((float4*)qrow)[tid] = s4;
    float s = s4.x + s4.y + s4.z + s4.w;
    float sq = s4.x * s4.x + s4.y * s4.y + s4.z * s4.z + s4.w * s4.w;
    red[tid] = make_float2(s, sq); __syncthreads();
    for (int st = 128; st > 0; st >>= 1) {
        if (tid < st) { red[tid].x += red[tid + st].x; red[tid].y += red[tid + st].y; }
        __syncthreads();
    }
    float mean = red[0].x * (1.f / 1024.f);
    float var  = red[0].y * (1.f / 1024.f) - mean * mean;
    float rstd = rsqrtf(var + 1e-5f);
    float4 gv = ((const float4*)lng)[tid];
    float4 bv = ((const float4*)lnb)[tid];
    float4 o;
    o.x = (s4.x - mean) * rstd * gv.x + bv.x;
    o.y = (s4.y - mean) * rstd * gv.y + bv.y;
    o.z = (s4.z - mean) * rstd * gv.z + bv.z;
    o.w = (s4.w - mean) * rstd * gv.w + bv.w;
    ((float4*)xrow)[tid] = o;
}

// ---------------- 2-token self-attention core --------------------------------
__global__ void k_selfattn(const float* __restrict__ t3, float* __restrict__ attn)
{
    int b = blockIdx.x, h = blockIdx.y, d = threadIdx.x;
    const float* r0 = t3 + (size_t)(b * 2 + 0) * 3072;
    const float* r1 = t3 + (size_t)(b * 2 + 1) * 3072;
    int j = h * 64 + d;
    float q0 = r0[j], k0 = r0[1024 + j], v0 = r0[2048 + j];
    float q1 = r1[j], k1 = r1[1024 + j], v1 = r1[2048 + j];
    __shared__ float sh[4][64];
    sh[0][d] = q0 * k0; sh[1][d] = q0 * k1; sh[2][d] = q1 * k0; sh[3][d] = q1 * k1;
    __syncthreads();
    for (int st = 32; st > 0; st >>= 1) {
        if (d < st) {
            #pragma unroll
            for (int i = 0; i < 4; i++) sh[i][d] += sh[i][d + st];
        }
        __syncthreads();
    }
    float s00 = sh[0][0] * 0.125f, s01 = sh[1][0] * 0.125f;
    float s10 = sh[2][0] * 0.125f, s11 = sh[3][0] * 0.125f;
    float m0 = fmaxf(s00, s01), m1 = fmaxf(s10, s11);
    float e00 = expf(s00 - m0), e01 = expf(s01 - m0);
    float e10 = expf(s10 - m1), e11 = expf(s11 - m1);
    float a00 = e00 / (e00 + e01), a01 = e01 / (e00 + e01);
    float a10 = e10 / (e10 + e11), a11 = e11 / (e10 + e11);
    attn[(size_t)(b * 2 + 0) * Dm + j] = a00 * v0 + a01 * v1;
    attn[(size_t)(b * 2 + 1) * Dm + j] = a10 * v0 + a11 * v1;
}

// ---------------- fold (merged g/s): u[b,h,:] = qp[b, h*64: ] @ wk_h ---------
__global__ void k_ufold(const float* __restrict__ qpg, const float* __restrict__ qps,
                        const float* __restrict__ wkg, const float* __restrict__ wks,
                        float* __restrict__ ug, float* __restrict__ us)
{
    const float* qp = blockIdx.z ? qps : qpg;
    const float* wk = blockIdx.z ? wks : wkg;
    float* u = blockIdx.z ? us : ug;
    int h = blockIdx.x;
    int e = blockIdx.y * 128 + threadIdx.x;
    __shared__ float qs[32][64];
    for (int i = threadIdx.x; i < 2048; i += 128)
        qs[i >> 6][i & 63] = qp[(size_t)(i >> 6) * Dm + h * 64 + (i & 63)];
    __syncthreads();
    float acc[32];
    #pragma unroll
    for (int b2 = 0; b2 < 32; b2++) acc[b2] = 0.f;
    for (int d = 0; d < 64; d++) {
        float w = wk[(size_t)(h * 64 + d) * Dm + e];
        #pragma unroll
        for (int b2 = 0; b2 < 32; b2++) acc[b2] += qs[b2][d] * w;
    }
    #pragma unroll
    for (int b2 = 0; b2 < 32; b2++) u[((size_t)b2 * Hh + h) * Dm + e] = acc[b2];
}

// ---------------- scores (merged frame/kv) -----------------------------------
__global__ __launch_bounds__(256) void k_scores(
    const float* __restrict__ frame, const float* __restrict__ kvs,
    const float* __restrict__ ug, const float* __restrict__ us,
    float* __restrict__ sg, float* __restrict__ ss)
{
    extern __shared__ float ush[];   // 64 KB
    int b = blockIdx.x, by = blockIdx.y, tid = threadIdx.x;
    const float* X; const float* u; float* s; int Nt, tile;
    if (by < 64) { X = frame; u = ug; s = sg; Nt = Nf; tile = by; }
    else         { X = kvs;   u = us; s = ss; Nt = Kv; tile = by - 64; }
    const float4* usrc = (const float4*)(u + (size_t)b * Hh * Dm);
    #pragma unroll
    for (int i = 0; i < 16; i++) ((float4*)ush)[tid + i * 256] = usrc[tid + i * 256];
    __syncthreads();
    int w = tid >> 5, lane = tid & 31;
    for (int tl = 0; tl < 2; tl++) {
        int n0 = tile * 64 + tl * 32 + w * 4;
        const ulonglong2* xp = (const ulonglong2*)(X + ((size_t)b * Nt + n0) * Dm);
        u64 acc[16][4];
        #pragma unroll
        for (int h = 0; h < 16; h++)
            #pragma unroll
            for (int t = 0; t < 4; t++) acc[h][t] = 0ULL;
        for (int i = 0; i < 8; i++) {
            ulonglong2 x0 = xp[0 * 256 + i * 32 + lane];
            ulonglong2 x1 = xp[1 * 256 + i * 32 + lane];
            ulonglong2 x2 = xp[2 * 256 + i * 32 + lane];
            ulonglong2 x3 = xp[3 * 256 + i * 32 + lane];
            #pragma unroll
            for (int h = 0; h < 16; h++) {
                ulonglong2 uv = *(const ulonglong2*)&ush[h * Dm + i * 128 + (lane << 2)];
                ffma2(acc[h][0], x0.x, uv.x); ffma2(acc[h][0], x0.y, uv.y);
                ffma2(acc[h][1], x1.x, uv.x); ffma2(acc[h][1], x1.y, uv.y);
                ffma2(acc[h][2], x2.x, uv.x); ffma2(acc[h][2], x2.y, uv.y);
                ffma2(acc[h][3], x3.x, uv.x); ffma2(acc[h][3], x3.y, uv.y);
            }
        }
        #pragma unroll
        for (int h = 0; h < 16; h++) {
            #pragma unroll
            for (int t = 0; t < 4; t++) {
                float v = sum2(acc[h][t]);
                #pragma unroll
                for (int off = 16; off; off >>= 1) v += __shfl_xor_sync(0xffffffffu, v, off);
                if (lane == 0) s[((size_t)b * Hh + h) * Nt + n0 + t] = v * 0.125f;
            }
        }
    }
}

// ---------------- softmax (merged frame/kv) ----------------------------------
template <int CNT>
__device__ __forceinline__ void softmax_row(float* __restrict__ s, float* red)
{
    int tid = threadIdx.x;
    float v[CNT];
    float mx = -1e30f;
    #pragma unroll
    for (int i = 0; i < CNT; i++) { v[i] = s[i * 256 + tid]; mx = fmaxf(mx, v[i]); }
    red[tid] = mx; __syncthreads();
    for (int st = 128; st > 0; st >>= 1) {
        if (tid < st) red[tid] = fmaxf(red[tid], red[tid + st]);
        __syncthreads();
    }
    mx = red[0]; __syncthreads();
    float sum = 0.f;
    #pragma unroll
    for (int i = 0; i < CNT; i++) { v[i] = expf(v[i] - mx); sum += v[i]; }
    red[tid] = sum; __syncthreads();
    for (int st = 128; st > 0; st >>= 1) {
        if (tid < st) red[tid] += red[tid + st];
        __syncthreads();
    }
    float inv = 1.f / red[0];
    #pragma unroll
    for (int i = 0; i < CNT; i++) s[i * 256 + tid] = v[i] * inv;
}

__global__ void k_softmax2(float* __restrict__ sg, float* __restrict__ ss)
{
    __shared__ float red[256];
    int id = blockIdx.x;
    if (id < 512) softmax_row<16>(sg + (size_t)id * Nf, red);
    else          softmax_row<4>(ss + (size_t)(id - 512) * Kv, red);
}

// ---------------- wbar partials (merged frame/kv, 2-token LDS.128) -----------
__global__ __launch_bounds__(256) void k_wbar(
    const float* __restrict__ frame, const float* __restrict__ kvs,
    const float* __restrict__ sg, const float* __restrict__ ss,
    float* __restrict__ wpart)
{
    __shared__ __align__(16) u64 ash[16][258];
    int b = blockIdx.x, sp = blockIdx.y, tid = threadIdx.x;
    const float* X; const float* a; int Nt, n0; float* dst;
    if (sp < 16) {
        X = frame; a = sg; Nt = Nf; n0 = sp * 256;
        dst = wpart + ((size_t)sp * Bsz + b) * (Hh * Dm);
    } else {
        int k2 = sp - 16;
        X = kvs; a = ss; Nt = Kv; n0 = k2 * 256;
        dst = wpart + WKV_OFF + ((size_t)k2 * Bsz + b) * (Hh * Dm);
    }
    for (int idx = tid; idx < 4096; idx += 256) {
        int nn = idx & 255, h = idx >> 8;
        ash[h][nn] = dup2(a[((size_t)b * Hh + h) * Nt + n0 + nn]);
    }
    __syncthreads();
    u64 acc[16][2];
    #pragma unroll
    for (int h = 0; h < 16; h++) { acc[h][0] = 0ULL; acc[h][1] = 0ULL; }
    const ulonglong2* xp = (const ulonglong2*)(X + ((size_t)b * Nt + n0) * Dm) + tid;
    for (int nn = 0; nn < 256; nn += 2) {
        ulonglong2 f0 = xp[(size_t)nn * 256];
        ulonglong2 f1 = xp[(size_t)(nn + 1) * 256];
        #pragma unroll
        for (int h = 0; h < 16; h++) {
            ulonglong2 ap = *(const ulonglong2*)&ash[h][nn];
            ffma2(acc[h][0], ap.x, f0.x);
            ffma2(acc[h][1], ap.x, f0.y);
            ffma2(acc[h][0], ap.y, f1.x);
            ffma2(acc[h][1], ap.y, f1.y);
        }
    }
    ulonglong2* P = (ulonglong2*)dst;
    #pragma unroll
    for (int h = 0; h < 16; h++) {
        ulonglong2 v; v.x = acc[h][0]; v.y = acc[h][1];
        P[h * 256 + tid] = v;
    }
}

// ---------------- v-projection (merged g/s, fused split reduce) --------------
__global__ void k_vproj(const float* __restrict__ wpart,
                        const float* __restrict__ wvg, const float* __restrict__ bvg,
                        const float* __restrict__ wvs, const float* __restrict__ bvs,
                        float* __restrict__ og, float* __restrict__ os)
{
    __shared__ float wsh[1024];
    int b = blockIdx.x, y = blockIdx.y, tid = threadIdx.x;
    int h, NS; const float* base; const float* wv; const float* bv; float* o;
    if (y < 16) { h = y;      NS = 16; base = wpart;           wv = wvg; bv = bvg; o = og; }
    else        { h = y - 16; NS = 4;  base = wpart + WKV_OFF; wv = wvs; bv = bvs; o = os; }
    float4 acc4 = make_float4(0.f, 0.f, 0.f, 0.f);
    for (int sp = 0; sp < NS; sp++) {
        float4 v = ((const float4*)(base + (((size_t)sp * Bsz + b) * Hh + h) * Dm))[tid];
        acc4.x += v.x; acc4.y += v.y; acc4.z += v.z; acc4.w += v.w;
    }
    ((float4*)wsh)[tid] = acc4;
    __syncthreads();
    int w = tid >> 5, lane = tid & 31;
    for (int dd = w; dd < 64; dd += 8) {
        int j = h * 64 + dd;
        const float4* wvp = (const float4*)(wv + (size_t)j * Dm);
        float acc = 0.f;
        #pragma unroll
        for (int i = 0; i < 8; i++) {
            float4 a = wvp[i * 32 + lane];
            float4 c = *(const float4*)&wsh[i * 128 + (lane << 2)];
            acc += a.x * c.x + a.y * c.y + a.z * c.z + a.w * c.w;
        }
        #pragma unroll
        for (int off = 16; off; off >>= 1) acc += __shfl_xor_sync(0xffffffffu, acc, off);
        if (lane == 0) o[(size_t)b * Dm + j] = acc + bv[j];
    }
}

extern "C" void kernel_launch(void* const* d_in, const int* in_sizes, int n_in,
                              void* d_out, int out_size)
{
    const float* frame = (const float*)d_in[0];
    const float* kvs   = (const float*)d_in[1];
    const float* maxi  = (const float*)d_in[2];
    const float* qbase = (const float*)d_in[3];
    const float* role  = (const float*)d_in[4];
    const float* timew = (const float*)d_in[5];
    const float* ln1g  = (const float*)d_in[6];
    const float* ln1b  = (const float*)d_in[7];
    const float* sa_in_w = (const float*)d_in[8];
    const float* sa_in_b = (const float*)d_in[9];
    const float* sa_out_w = (const float*)d_in[10];
    const float* sa_out_b = (const float*)d_in[11];
    const float* ln2g  = (const float*)d_in[12];
    const float* ln2b  = (const float*)d_in[13];
    const float* cg_in_w = (const float*)d_in[14];
    const float* cg_in_b = (const float*)d_in[15];
    const float* cg_out_w = (const float*)d_in[16];
    const float* cg_out_b = (const float*)d_in[17];
    const float* cs_in_w = (const float*)d_in[18];
    const float* cs_in_b = (const float*)d_in[19];
    const float* cs_out_w = (const float*)d_in[20];
    const float* cs_out_b = (const float*)d_in[21];
    const float* ln3g  = (const float*)d_in[22];
    const float* ln3b  = (const float*)d_in[23];
    const float* fw1   = (const float*)d_in[24];
    const float* fb1   = (const float*)d_in[25];
    const float* fw2   = (const float*)d_in[26];
    const float* fb2   = (const float*)d_in[27];
    const float* outg  = (const float*)d_in[28];
    const float* outb  = (const float*)d_in[29];
    const int*   fidx  = (const int*)d_in[30];
    float* outp = (float*)d_out;

    void* sp_;
    cudaGetSymbolAddress(&sp_, g_scratch);
    float* S = (float*)sp_;
    float* mpart = S;                   // 524288
    float* q     = mpart + 524288;      // 65536
    float* x     = q + 65536;           // 65536
    float* t3    = x + 65536;           // 196608
    float* attn  = t3 + 196608;         // 65536
    float* qpg   = attn + 65536;        // 32768
    float* qps   = qpg + 32768;         // 32768
    float* ug    = qps + 32768;         // 524288
    float* us    = ug + 524288;         // 524288
    float* sg    = us + 524288;         // 2097152
    float* ss    = sg + 2097152;        // 524288
    float* wpart = ss + 524288;         // 10485760 (frame 16 + kv 4 chunks)
    float* og    = wpart + 10485760;    // 32768
    float* os    = og + 32768;          // 32768
    float* gpart = os + 32768;          // 3145728
    float* hh    = gpart + 3145728;     // 262144

    cudaFuncSetAttribute(k_scores, cudaFuncAttributeMaxDynamicSharedMemorySize, 65536);

    // init: mean + q assembly + first LN
    k_mean_part<<<dim3(32, 16), 256>>>(frame, mpart);
    k_qinit<<<32, 256>>>(mpart, maxi, qbase, role, timew, fidx, q);
    k_ln<<<64, 256>>>(q, ln1g, ln1b, x);

    for (int l = 0; l < 2; l++) {
        const float* siw = sa_in_w + (size_t)l * 3072 * Dm;
        const float* sib = sa_in_b + l * 3072;
        const float* sow = sa_out_w + (size_t)l * Dm * Dm;
        const float* sob = sa_out_b + l * Dm;
        const float* l2g = ln2g + l * Dm;   const float* l2b = ln2b + l * Dm;
        const float* giw = cg_in_w + (size_t)l * 3072 * Dm;
        const float* gib = cg_in_b + l * 3072;
        const float* gow = cg_out_w + (size_t)l * Dm * Dm;
        const float* gob = cg_out_b + l * Dm;
        const float* ciw = cs_in_w + (size_t)l * 3072 * Dm;
        const float* cib = cs_in_b + l * 3072;
        const float* cow = cs_out_w + (size_t)l * Dm * Dm;
        const float* cob = cs_out_b + l * Dm;
        const float* l3g = ln3g + l * Dm;   const float* l3b = ln3b + l * Dm;
        const float* w1 = fw1 + (size_t)l * 4096 * Dm;
        const float* b1 = fb1 + l * 4096;
        const float* w2 = fw2 + (size_t)l * Dm * 4096;
        const float* b2 = fb2 + l * Dm;
        const float* nlg = (l == 0) ? (ln1g + Dm) : outg;
        const float* nlb = (l == 0) ? (ln1b + Dm) : outb;
        float* nx = (l == 0) ? x : outp;

        // ---- self-attention (2 tokens): x is LN1(q) ----
        k_gemmp2<64><<<dim3(24, 1, 8), 256>>>(x, 1024, siw, 1024, nullptr, nullptr,
                                              gpart, 3072, 128, 64);
        k_gemm_reduce<<<dim3(12, 64), 256>>>(gpart, t3, 3072, sib, 64, 3072, 8, 0);
        k_selfattn<<<dim3(32, 16), 64>>>(t3, attn);
        k_gemmp2<64><<<dim3(8, 1, 16), 256>>>(attn, 1024, sow, 1024, nullptr, nullptr,
                                              gpart, 1024, 64, 64);
        k_reduce_ln<<<64, 256>>>(gpart, 64, 16, sob, q, 1024, l2g, l2b, x, 1024);

        // ---- cross-attention (folded K/V), g+s paired ----
        k_gemmp2<32><<<dim3(8, 2, 16), 256>>>(x, 2048, giw, 1024, x + 1024, ciw,
                                              gpart, 1024, 64, 64);
        k_reduce_pair<<<dim3(4, 64), 256>>>(gpart, 16, gib, cib, qpg, qps);
        k_ufold<<<dim3(16, 8, 2), 128>>>(qpg, qps, giw + 1024 * 1024, ciw + 1024 * 1024, ug, us);
        k_scores<<<dim3(32, 80), 256, 65536>>>(frame, kvs, ug, us, sg, ss);
        k_softmax2<<<1024, 256>>>(sg, ss);
        k_wbar<<<dim3(32, 20), 256>>>(frame, kvs, sg, ss, wpart);
        k_vproj<<<dim3(32, 32), 256>>>(wpart, giw + 2 * 1024 * 1024, gib + 2048,
                                       ciw + 2 * 1024 * 1024, cib + 2048, og, os);
        k_gemmp2<32><<<dim3(8, 2, 16), 256>>>(og, 1024, gow, 1024, os, cow,
                                              gpart, 1024, 64, 64);
        k_reduce_ln_pair<<<64, 256>>>(gpart, 16, gob, cob, q, l3g, l3b, x);

        // ---- FFN: x is LN3(q) ----
        k_gemmp2<64><<<dim3(32, 1, 8), 256>>>(x, 1024, w1, 1024, nullptr, nullptr,
                                              gpart, 4096, 128, 64);
        k_gemm_reduce<<<dim3(16, 64), 256>>>(gpart, hh, 4096, b1, 64, 4096, 8, 1);
        k_gemmp2<64><<<dim3(8, 1, 32), 256>>>(hh, 4096, w2, 4096, nullptr, nullptr,
                                              gpart, 1024, 128, 64);
        k_reduce_ln<<<64, 256>>>(gpart, 64, 32, b2, q, 1024, nlg, nlb, nx, 1024);
    }
}